// round 1
// baseline (speedup 1.0000x reference)
#include <cuda_runtime.h>
#include <cuda_bf16.h>

// Problem constants
#define DIMC 256
#define EMBC 512
#define DHC 32
#define HC 8
#define NTOK 49
#define NWIN 2048
#define WPB 256              // windows per batch (16*16)
#define QSCALE 0.1767766952966369f   // 32^-0.5

// Scratch (allocation-free rule: __device__ globals)
__device__ float g_mod[8 * 768];            // per batch: [gamma(256) beta(256) sigma(256)]
__device__ float g_wT[4 * DIMC * DIMC];     // q,k,v,o transposed: wT[w][d][c] = W[c][d] (q pre-scaled)
__device__ float g_bias[HC * NTOK * NTOK];  // [h][i][j]

// Smem layout for main kernel (floats)
#define SX_STRIDE 260                        // 49 x 260 (16B-aligned rows, float4 reads)
#define SH_STRIDE 33                         // per-head [49][33]: bank = (j + d) % 32, conflict-free
#define SX_FLOATS (NTOK * SX_STRIDE)         // 12740
#define SH_FLOATS (HC * NTOK * SH_STRIDE)    // 12936
#define SMEM_FLOATS (SX_FLOATS + 3 * SH_FLOATS)
#define SMEM_BYTES (SMEM_FLOATS * 4)         // 206,192 B

// ---------------------------------------------------------------------------
// Prep kernels (tiny)
// ---------------------------------------------------------------------------
__global__ void prep_mod(const float* __restrict__ emb, const float* __restrict__ proj_w) {
    __shared__ float se[EMBC];
    int b = blockIdx.x;
    for (int i = threadIdx.x; i < EMBC; i += 256) se[i] = emb[b * EMBC + i];
    __syncthreads();
    for (int r = 0; r < 3; r++) {
        int o = r * 256 + threadIdx.x;
        const float* row = proj_w + (size_t)o * EMBC;
        float s = 0.f;
        #pragma unroll 8
        for (int e = 0; e < EMBC; e++) s = fmaf(row[e], se[e], s);
        g_mod[b * 768 + o] = s;
    }
}

__global__ void prep_w(const float* __restrict__ wq, const float* __restrict__ wk,
                       const float* __restrict__ wv, const float* __restrict__ wo) {
    int wsel = blockIdx.y;       // 0..3
    int d = blockIdx.x;          // 0..255
    int c = threadIdx.x;         // 0..255
    const float* W = (wsel == 0) ? wq : (wsel == 1) ? wk : (wsel == 2) ? wv : wo;
    float scale = (wsel == 0) ? QSCALE : 1.f;
    g_wT[(wsel * DIMC + d) * DIMC + c] = W[c * DIMC + d] * scale;
}

__global__ void prep_bias(const float* __restrict__ bt) {
    int idx = blockIdx.x * 256 + threadIdx.x;
    if (idx >= HC * NTOK * NTOK) return;
    int h = idx / (NTOK * NTOK);
    int r = idx % (NTOK * NTOK);
    int i = r / NTOK, j = r % NTOK;
    int rel = (i / 7 - j / 7 + 6) * 13 + (i % 7 - j % 7 + 6);
    g_bias[idx] = bt[rel * HC + h];
}

// ---------------------------------------------------------------------------
// 49x256 @ 256x256 GEMM: thread owns one output column c, 49 accumulators.
// wT is [256][256] in gmem (L2-resident), sIn is [49][SX_STRIDE] in smem.
// ---------------------------------------------------------------------------
__device__ __forceinline__ void gemm49(const float* __restrict__ wT,
                                       const float* __restrict__ sIn,
                                       float* acc, int c) {
    #pragma unroll
    for (int i = 0; i < NTOK; i++) acc[i] = 0.f;
    const float* wcol = wT + c;
    float w0 = wcol[0], w1 = wcol[DIMC], w2 = wcol[2 * DIMC], w3 = wcol[3 * DIMC];
    for (int d = 0; d < DIMC; d += 4) {
        float nw0 = 0.f, nw1 = 0.f, nw2 = 0.f, nw3 = 0.f;
        if (d + 4 < DIMC) {
            const float* p = wcol + (size_t)(d + 4) * DIMC;
            nw0 = p[0]; nw1 = p[DIMC]; nw2 = p[2 * DIMC]; nw3 = p[3 * DIMC];
        }
        #pragma unroll
        for (int i = 0; i < NTOK; i++) {
            float4 xv = *(const float4*)(sIn + i * SX_STRIDE + d);
            float a = acc[i];
            a = fmaf(xv.x, w0, a);
            a = fmaf(xv.y, w1, a);
            a = fmaf(xv.z, w2, a);
            a = fmaf(xv.w, w3, a);
            acc[i] = a;
        }
        w0 = nw0; w1 = nw1; w2 = nw2; w3 = nw3;
    }
}

// ---------------------------------------------------------------------------
// Main fused kernel: one block per window
// ---------------------------------------------------------------------------
extern __shared__ float smem[];

__global__ __launch_bounds__(256, 1)
void fused_win_attn(const float* __restrict__ x,
                    const float* __restrict__ ln_w,
                    const float* __restrict__ ln_b,
                    float* __restrict__ out) {
    float* sX = smem;                    // [49][260]; LN output, later attention output
    float* sQ = smem + SX_FLOATS;        // [8][49][33]
    float* sK = sQ + SH_FLOATS;
    float* sV = sK + SH_FLOATS;

    const int w = blockIdx.x;
    const int b = w >> 8;                // w / 256
    const int tid = threadIdx.x;
    const int lane = tid & 31;
    const int warp = tid >> 5;

    const float* xwin = x + (size_t)w * NTOK * DIMC;
    const float* gamma = g_mod + b * 768;
    const float* beta  = gamma + 256;

    // ---- Phase 1: LayerNorm + AdaLN modulation -> sX ----
    for (int i = warp; i < NTOK; i += 8) {
        float v[8], s = 0.f;
        #pragma unroll
        for (int k = 0; k < 8; k++) { v[k] = xwin[i * DIMC + k * 32 + lane]; s += v[k]; }
        #pragma unroll
        for (int off = 16; off; off >>= 1) s += __shfl_xor_sync(0xffffffffu, s, off);
        float mu = s * (1.f / 256.f);
        float s2 = 0.f;
        #pragma unroll
        for (int k = 0; k < 8; k++) { float t = v[k] - mu; s2 = fmaf(t, t, s2); }
        #pragma unroll
        for (int off = 16; off; off >>= 1) s2 += __shfl_xor_sync(0xffffffffu, s2, off);
        float rstd = rsqrtf(s2 * (1.f / 256.f) + 1e-5f);
        #pragma unroll
        for (int k = 0; k < 8; k++) {
            int d = k * 32 + lane;
            float xn = (v[k] - mu) * rstd * ln_w[d] + ln_b[d];
            sX[i * SX_STRIDE + d] = fmaf(xn, 1.f + gamma[d], beta[d]);
        }
    }
    __syncthreads();

    // ---- Phase 2: Q,K,V projections ----
    const int c = tid;
    const int h = c >> 5, dd = c & 31;
    float acc[NTOK];

    gemm49(g_wT + 0 * DIMC * DIMC, sX, acc, c);
    {
        float* dst = sQ + h * (NTOK * SH_STRIDE) + dd;
        #pragma unroll
        for (int i = 0; i < NTOK; i++) dst[i * SH_STRIDE] = acc[i];
    }
    gemm49(g_wT + 1 * DIMC * DIMC, sX, acc, c);
    {
        float* dst = sK + h * (NTOK * SH_STRIDE) + dd;
        #pragma unroll
        for (int i = 0; i < NTOK; i++) dst[i * SH_STRIDE] = acc[i];
    }
    gemm49(g_wT + 2 * DIMC * DIMC, sX, acc, c);
    {
        float* dst = sV + h * (NTOK * SH_STRIDE) + dd;
        #pragma unroll
        for (int i = 0; i < NTOK; i++) dst[i * SH_STRIDE] = acc[i];
    }
    __syncthreads();

    // ---- Phase 3: attention, one warp per head; output -> sX columns ----
    {
        const float* qh = sQ + warp * (NTOK * SH_STRIDE);
        const float* kh = sK + warp * (NTOK * SH_STRIDE);
        const float* vh = sV + warp * (NTOK * SH_STRIDE);
        const float* bh = g_bias + warp * (NTOK * NTOK);
        const bool has2 = (lane < 17);
        const int j1 = has2 ? (lane + 32) : 48;    // clamp: avoid smem OOB

        for (int i = 0; i < NTOK; i++) {
            float s0 = 0.f, s1 = 0.f;
            const float* qrow = qh + i * SH_STRIDE;
            #pragma unroll
            for (int d = 0; d < DHC; d++) {
                float qv = qrow[d];                        // broadcast LDS
                s0 = fmaf(qv, kh[lane * SH_STRIDE + d], s0);
                s1 = fmaf(qv, kh[j1 * SH_STRIDE + d], s1);
            }
            s0 += bh[i * NTOK + lane];
            float m;
            if (has2) { s1 += bh[i * NTOK + 32 + lane]; m = fmaxf(s0, s1); }
            else      { m = s0; }
            #pragma unroll
            for (int off = 16; off; off >>= 1)
                m = fmaxf(m, __shfl_xor_sync(0xffffffffu, m, off));
            float p0 = __expf(s0 - m);
            float p1 = has2 ? __expf(s1 - m) : 0.f;
            float sum = p0 + p1;
            #pragma unroll
            for (int off = 16; off; off >>= 1)
                sum += __shfl_xor_sync(0xffffffffu, sum, off);
            float inv = 1.f / sum;
            p0 *= inv; p1 *= inv;
            float o = 0.f;
            #pragma unroll
            for (int j = 0; j < NTOK; j++) {
                float pj = (j < 32) ? __shfl_sync(0xffffffffu, p0, j)
                                    : __shfl_sync(0xffffffffu, p1, j - 32);
                o = fmaf(pj, vh[j * SH_STRIDE + lane], o);
            }
            sX[i * SX_STRIDE + warp * 32 + lane] = o;
        }
    }
    __syncthreads();

    // ---- Phase 4: output projection * sigma ----
    gemm49(g_wT + 3 * DIMC * DIMC, sX, acc, c);
    float sg = g_mod[b * 768 + 512 + c];
    float* outw = out + (size_t)w * NTOK * DIMC;
    #pragma unroll
    for (int i = 0; i < NTOK; i++) outw[i * DIMC + c] = acc[i] * sg;
}

// ---------------------------------------------------------------------------
extern "C" void kernel_launch(void* const* d_in, const int* in_sizes, int n_in,
                              void* d_out, int out_size) {
    const float* x      = (const float*)d_in[0];
    const float* emb    = (const float*)d_in[1];
    const float* ln_w   = (const float*)d_in[2];
    const float* ln_b   = (const float*)d_in[3];
    const float* proj_w = (const float*)d_in[4];
    const float* wq     = (const float*)d_in[5];
    const float* wk     = (const float*)d_in[6];
    const float* wv     = (const float*)d_in[7];
    const float* wo     = (const float*)d_in[8];
    const float* bt     = (const float*)d_in[9];
    float* out = (float*)d_out;

    prep_mod<<<8, 256>>>(emb, proj_w);
    prep_w<<<dim3(256, 4), 256>>>(wq, wk, wv, wo);
    prep_bias<<<(HC * NTOK * NTOK + 255) / 256, 256>>>(bt);

    cudaFuncSetAttribute(fused_win_attn,
                         cudaFuncAttributeMaxDynamicSharedMemorySize, SMEM_BYTES);
    fused_win_attn<<<NWIN, 256, SMEM_BYTES>>>(x, ln_w, ln_b, out);
}

// round 2
// speedup vs baseline: 1.2414x; 1.2414x over previous
#include <cuda_runtime.h>
#include <cuda_bf16.h>

// Problem constants
#define DIMC 256
#define EMBC 512
#define HC 8
#define NTOK 49
#define NWIN 2048
#define QSCALE 0.1767766952966369f   // 32^-0.5

#define ST 60            // sXT row stride in floats: [256 d][60] (16B aligned, 4-way write conflicts only)
#define SH_STRIDE 33     // per-head [49][33]: conflict-free attention reads
#define HALF_T 28        // tokens per thread-half (49 padded to 56)
#define NPAIR 14         // token-pairs per thread-half

// Scratch (allocation-free rule: __device__ globals)
__device__ float  g_mod[8 * 768];                 // per batch: gamma|beta|sigma
__device__ float2 g_w2[4 * 8 * DIMC * 16];        // [wsel][colblock8][d256][cpl16] = (W[c0][d], W[c0+1][d])
__device__ float  g_bias[HC * NTOK * NTOK];       // [h][i][j]

#define SXT_FLOATS (DIMC * ST)                    // 15360
#define SH_FLOATS  (HC * NTOK * SH_STRIDE)        // 12936
#define SMEM_BYTES ((SXT_FLOATS + 3 * SH_FLOATS) * 4)   // 216,672 B

// ---------------------------------------------------------------------------
// Prep kernels
// ---------------------------------------------------------------------------
__global__ void prep_mod(const float* __restrict__ emb, const float* __restrict__ proj_w) {
    __shared__ float se[EMBC];
    int b = blockIdx.x;
    for (int i = threadIdx.x; i < EMBC; i += 256) se[i] = emb[b * EMBC + i];
    __syncthreads();
    for (int r = 0; r < 3; r++) {
        int o = r * 256 + threadIdx.x;
        const float* row = proj_w + (size_t)o * EMBC;
        float s = 0.f;
        #pragma unroll 8
        for (int e = 0; e < EMBC; e++) s = fmaf(row[e], se[e], s);
        g_mod[b * 768 + o] = s;
    }
}

// Weight relayout: per warp-colblock, the 16 col-pairs for one d are contiguous (128B line).
__global__ void prep_w2(const float* __restrict__ wq, const float* __restrict__ wk,
                        const float* __restrict__ wv, const float* __restrict__ wo) {
    int wsel = blockIdx.y;
    int idx = blockIdx.x * 256 + threadIdx.x;        // [0, 32768)
    const float* W = (wsel == 0) ? wq : (wsel == 1) ? wk : (wsel == 2) ? wv : wo;
    float s = (wsel == 0) ? QSCALE : 1.f;
    int cb  = idx >> 12;          // colblock 0..7
    int rem = idx & 4095;
    int d   = rem >> 4;           // 0..255
    int cpl = rem & 15;           // col-pair-in-block
    int c0  = cb * 32 + cpl * 2;
    g_w2[((size_t)(wsel * 8 + cb) * DIMC + d) * 16 + cpl] =
        make_float2(W[c0 * DIMC + d] * s, W[(c0 + 1) * DIMC + d] * s);
}

__global__ void prep_bias(const float* __restrict__ bt) {
    int idx = blockIdx.x * 256 + threadIdx.x;
    if (idx >= HC * NTOK * NTOK) return;
    int h = idx / (NTOK * NTOK);
    int r = idx % (NTOK * NTOK);
    int i = r / NTOK, j = r % NTOK;
    int rel = (i / 7 - j / 7 + 6) * 13 + (i % 7 - j % 7 + 6);
    g_bias[idx] = bt[rel * HC + h];
}

// ---------------------------------------------------------------------------
// Packed fp32 helpers
// ---------------------------------------------------------------------------
__device__ __forceinline__ unsigned long long ffma2(unsigned long long a,
                                                    unsigned long long b,
                                                    unsigned long long c) {
    unsigned long long d;
    asm("fma.rn.f32x2 %0, %1, %2, %3;" : "=l"(d) : "l"(a), "l"(b), "l"(c));
    return d;
}
#define SPLAT2(dst, w) asm("mov.b64 %0, {%1, %1};" : "=l"(dst) : "f"(w))
#define UNPK(lo, hi, v) asm("mov.b64 {%0, %1}, %2;" : "=f"(lo), "=f"(hi) : "l"(v))

// ---------------------------------------------------------------------------
// 56x2-per-thread GEMM over K=256: thread owns cols (c0,c0+1) and 28 tokens.
// wrow: pre-offset &g_w2[(wsel*8+cb)*256*16 + cpl]; stride per d = 16 float2.
// xb:   sXT + half*28 (transposed activations [d][token], padded zeros 49..55)
// ---------------------------------------------------------------------------
__device__ __forceinline__ void gemm2(const float2* __restrict__ wrow,
                                      const float* __restrict__ xb,
                                      unsigned long long* accA,
                                      unsigned long long* accB) {
    #pragma unroll
    for (int j = 0; j < NPAIR; j++) { accA[j] = 0ull; accB[j] = 0ull; }
    for (int d = 0; d < DIMC; d += 4) {
        float2 wv[4];
        #pragma unroll
        for (int u = 0; u < 4; u++) wv[u] = wrow[(size_t)(d + u) * 16];
        #pragma unroll
        for (int u = 0; u < 4; u++) {
            unsigned long long wa, wb;
            SPLAT2(wa, wv[u].x);
            SPLAT2(wb, wv[u].y);
            const ulonglong2* xp = (const ulonglong2*)(xb + (size_t)(d + u) * ST);
            #pragma unroll
            for (int t = 0; t < 7; t++) {
                ulonglong2 xv = xp[t];
                accA[2 * t]     = ffma2(xv.x, wa, accA[2 * t]);
                accA[2 * t + 1] = ffma2(xv.y, wa, accA[2 * t + 1]);
                accB[2 * t]     = ffma2(xv.x, wb, accB[2 * t]);
                accB[2 * t + 1] = ffma2(xv.y, wb, accB[2 * t + 1]);
            }
        }
    }
}

// ---------------------------------------------------------------------------
// Main fused kernel: one block per window
// ---------------------------------------------------------------------------
extern __shared__ float smem[];

__global__ __launch_bounds__(256, 1)
void fused_win_attn(const float* __restrict__ x,
                    const float* __restrict__ ln_w,
                    const float* __restrict__ ln_b,
                    float* __restrict__ out) {
    float* sXT = smem;                  // [256][ST] transposed activations / attn output
    float* sQ  = smem + SXT_FLOATS;     // [8][49][33]
    float* sK  = sQ + SH_FLOATS;
    float* sV  = sK + SH_FLOATS;

    const int w = blockIdx.x;
    const int b = w >> 8;
    const int tid = threadIdx.x;
    const int lane = tid & 31;
    const int warp = tid >> 5;

    const float* xwin  = x + (size_t)w * NTOK * DIMC;
    const float* gamma = g_mod + b * 768;
    const float* beta  = gamma + 256;

    // ---- zero-pad tokens 49..55 in sXT ----
    #pragma unroll
    for (int r = 0; r < 7; r++) {
        int idx = r * 256 + tid;        // 0..1791
        int d = idx / 7, i = idx % 7;
        sXT[d * ST + 49 + i] = 0.f;
    }

    // ---- Phase 1: LayerNorm + AdaLN -> sXT (transposed) ----
    for (int i = warp; i < NTOK; i += 8) {
        float v[8], s = 0.f;
        #pragma unroll
        for (int k = 0; k < 8; k++) { v[k] = xwin[i * DIMC + k * 32 + lane]; s += v[k]; }
        #pragma unroll
        for (int off = 16; off; off >>= 1) s += __shfl_xor_sync(0xffffffffu, s, off);
        float mu = s * (1.f / 256.f);
        float s2 = 0.f;
        #pragma unroll
        for (int k = 0; k < 8; k++) { float t = v[k] - mu; s2 = fmaf(t, t, s2); }
        #pragma unroll
        for (int off = 16; off; off >>= 1) s2 += __shfl_xor_sync(0xffffffffu, s2, off);
        float rstd = rsqrtf(s2 * (1.f / 256.f) + 1e-5f);
        #pragma unroll
        for (int k = 0; k < 8; k++) {
            int d = k * 32 + lane;
            float xn = (v[k] - mu) * rstd * ln_w[d] + ln_b[d];
            sXT[d * ST + i] = fmaf(xn, 1.f + gamma[d], beta[d]);
        }
    }
    __syncthreads();

    // ---- Phase 2: Q,K,V projections (FFMA2 register-tiled GEMM) ----
    const int half  = tid & 1;
    const int cpair = tid >> 1;
    const int cb    = cpair >> 4;       // colblock = head
    const int cpl   = cpair & 15;
    const int c0    = cb * 32 + cpl * 2;
    const int dd    = cpl * 2;
    const float* xb = sXT + half * HALF_T;

    unsigned long long accA[NPAIR], accB[NPAIR];

    #pragma unroll 1
    for (int g = 0; g < 3; g++) {
        const float2* wrow = g_w2 + ((size_t)(g * 8 + cb) * DIMC) * 16 + cpl;
        gemm2(wrow, xb, accA, accB);
        float* base = ((g == 0) ? sQ : (g == 1) ? sK : sV) + cb * (NTOK * SH_STRIDE) + dd;
        #pragma unroll
        for (int j = 0; j < NPAIR; j++) {
            float a0, a1, b0, b1;
            UNPK(a0, a1, accA[j]);
            UNPK(b0, b1, accB[j]);
            int i0 = half * HALF_T + 2 * j;
            if (i0 < NTOK)     { base[i0 * SH_STRIDE] = a0;       base[i0 * SH_STRIDE + 1] = b0; }
            if (i0 + 1 < NTOK) { base[(i0 + 1) * SH_STRIDE] = a1; base[(i0 + 1) * SH_STRIDE + 1] = b1; }
        }
    }
    __syncthreads();

    // ---- Phase 3: attention, one warp per head; output -> sXT (transposed) ----
    {
        const float* qh = sQ + warp * (NTOK * SH_STRIDE);
        const float* kh = sK + warp * (NTOK * SH_STRIDE);
        const float* vh = sV + warp * (NTOK * SH_STRIDE);
        const float* bh = g_bias + warp * (NTOK * NTOK);
        const bool has2 = (lane < 17);
        const int j1 = has2 ? (lane + 32) : 48;

        for (int i = 0; i < NTOK; i++) {
            float s0 = 0.f, s1 = 0.f;
            const float* qrow = qh + i * SH_STRIDE;
            #pragma unroll
            for (int d = 0; d < 32; d++) {
                float qv = qrow[d];
                s0 = fmaf(qv, kh[lane * SH_STRIDE + d], s0);
                s1 = fmaf(qv, kh[j1 * SH_STRIDE + d], s1);
            }
            s0 += bh[i * NTOK + lane];
            float m;
            if (has2) { s1 += bh[i * NTOK + 32 + lane]; m = fmaxf(s0, s1); }
            else      { m = s0; }
            #pragma unroll
            for (int off = 16; off; off >>= 1)
                m = fmaxf(m, __shfl_xor_sync(0xffffffffu, m, off));
            float p0 = __expf(s0 - m);
            float p1 = has2 ? __expf(s1 - m) : 0.f;
            float sum = p0 + p1;
            #pragma unroll
            for (int off = 16; off; off >>= 1)
                sum += __shfl_xor_sync(0xffffffffu, sum, off);
            float inv = 1.f / sum;
            p0 *= inv; p1 *= inv;
            float o = 0.f;
            #pragma unroll
            for (int j = 0; j < NTOK; j++) {
                float pj = (j < 32) ? __shfl_sync(0xffffffffu, p0, j)
                                    : __shfl_sync(0xffffffffu, p1, j - 32);
                o = fmaf(pj, vh[j * SH_STRIDE + lane], o);
            }
            sXT[(warp * 32 + lane) * ST + i] = o;   // padded tokens 49..55 untouched (stay 0)
        }
    }
    __syncthreads();

    // ---- Phase 4: output projection * sigma ----
    {
        const float2* wrow = g_w2 + ((size_t)(3 * 8 + cb) * DIMC) * 16 + cpl;
        gemm2(wrow, xb, accA, accB);
        float sg0 = g_mod[b * 768 + 512 + c0];
        float sg1 = g_mod[b * 768 + 512 + c0 + 1];
        float* outw = out + (size_t)w * NTOK * DIMC + c0;
        #pragma unroll
        for (int j = 0; j < NPAIR; j++) {
            float a0, a1, b0, b1;
            UNPK(a0, a1, accA[j]);
            UNPK(b0, b1, accB[j]);
            int i0 = half * HALF_T + 2 * j;
            if (i0 < NTOK)     *(float2*)(outw + (size_t)i0 * DIMC)       = make_float2(a0 * sg0, b0 * sg1);
            if (i0 + 1 < NTOK) *(float2*)(outw + (size_t)(i0 + 1) * DIMC) = make_float2(a1 * sg0, b1 * sg1);
        }
    }
}

// ---------------------------------------------------------------------------
extern "C" void kernel_launch(void* const* d_in, const int* in_sizes, int n_in,
                              void* d_out, int out_size) {
    const float* x      = (const float*)d_in[0];
    const float* emb    = (const float*)d_in[1];
    const float* ln_w   = (const float*)d_in[2];
    const float* ln_b   = (const float*)d_in[3];
    const float* proj_w = (const float*)d_in[4];
    const float* wq     = (const float*)d_in[5];
    const float* wk     = (const float*)d_in[6];
    const float* wv     = (const float*)d_in[7];
    const float* wo     = (const float*)d_in[8];
    const float* bt     = (const float*)d_in[9];
    float* out = (float*)d_out;

    prep_mod<<<8, 256>>>(emb, proj_w);
    prep_w2<<<dim3(128, 4), 256>>>(wq, wk, wv, wo);
    prep_bias<<<(HC * NTOK * NTOK + 255) / 256, 256>>>(bt);

    cudaFuncSetAttribute(fused_win_attn,
                         cudaFuncAttributeMaxDynamicSharedMemorySize, SMEM_BYTES);
    fused_win_attn<<<NWIN, 256, SMEM_BYTES>>>(x, ln_w, ln_b, out);
}